// round 2
// baseline (speedup 1.0000x reference)
#include <cuda_runtime.h>
#include <cstdint>

// ============================================================================
// RetinaHead: 5 FPN levels, two conv towers (cls 720ch / reg 36ch), postprocess.
// fp32 implicit-GEMM conv (9 shifted GEMMs), uniform [C][B*HW] layout.
// ============================================================================

#define NUM_CLASSES 80
#define NUM_ANCH 9
#define ATOT 49104      // sum over levels of HW*9
#define BATCH 8
#define NMAX (256*32768)

// Scratch (static device memory; no allocation at runtime)
__device__ float g_x[NMAX];                 // transposed input feat [256][N]
__device__ float g_a[NMAX];                 // ping
__device__ float g_b[NMAX];                 // pong
__device__ float g_cls[720 * 32768];        // cls logits [720][N] (per level)
__device__ float g_reg[36 * 32768];         // reg deltas [36][N]
__device__ float g_wt[6460416];             // transposed weights [kpos][cin][cout]

// Weight transform: src (Cout,256,3,3) -> dst [kpos][cin][cout]
__global__ void wt_kernel(const float* __restrict__ src, float* __restrict__ dst, int Cout) {
    int total = 9 * 256 * Cout;
    for (int t = blockIdx.x * blockDim.x + threadIdx.x; t < total; t += gridDim.x * blockDim.x) {
        int cout = t % Cout;
        int rem  = t / Cout;
        int cin  = rem % 256;
        int kpos = rem / 256;
        dst[t] = src[(cout * 256 + cin) * 9 + kpos];
    }
}

// Transpose feat (B,256,H,W) -> [256][B*HW]
__global__ void transpose_feat(const float* __restrict__ src, float* __restrict__ dst,
                               int HW, int N) {
    int total = 256 * N;
    for (int t = blockIdx.x * blockDim.x + threadIdx.x; t < total; t += gridDim.x * blockDim.x) {
        int c   = t / N;
        int rem = t % N;
        int b   = rem / HW;
        int p   = rem % HW;
        dst[t] = src[(b * 256 + c) * HW + p];
    }
}

// conv3x3 SAME (Cin=256) as 9 shifted GEMMs.
// X: [256][N], Y: [Cout][N]. WT: [kpos][cin][Cout]. Tile: 128 cout x 64 pix x 32 cin.
__global__ void __launch_bounds__(256)
conv3x3_kernel(const float* __restrict__ WT, const float* __restrict__ bias,
               const float* __restrict__ X, float* __restrict__ Y,
               int Cout, int N, int W, int logW, int H, int doRelu) {
    __shared__ float As[32][128];
    __shared__ float Bs[32][64];

    const int tid = threadIdx.x;
    const int n0 = blockIdx.x * 64;
    const int m0 = blockIdx.y * 128;
    const int tx = tid & 15;        // pixel dir, 4 each
    const int ty = tid >> 4;        // cout dir, 8 each

    float acc[8][4];
#pragma unroll
    for (int i = 0; i < 8; i++)
#pragma unroll
        for (int j = 0; j < 4; j++) acc[i][j] = 0.f;

    // B-load geometry (per-thread fixed column)
    const int bcol = tid & 63;
    const int brow0 = tid >> 6;     // 0..3
    const int n_g = n0 + bcol;
    const int xc = n_g & (W - 1);
    const int yc = (n_g >> logW) & (H - 1);

    // A-load geometry
    const int acol = tid & 127;
    const int arow0 = tid >> 7;     // 0..1
    const bool mvalid = (m0 + acol) < Cout;

    for (int kpos = 0; kpos < 9; kpos++) {
        const int dy = kpos / 3 - 1;
        const int dx = kpos % 3 - 1;
        const int off = dy * W + dx;
        const bool ok = (xc + dx >= 0) && (xc + dx < W) && (yc + dy >= 0) && (yc + dy < H);
        const float* Xq = X + n_g + off;
        const float* Wp = WT + (kpos * 256) * Cout + m0 + acol;

        for (int kc = 0; kc < 8; kc++) {
            // load A tile: 32 rows (cin) x 128 cols (cout)
            const float* WpK = Wp + (kc * 32) * Cout;
            const float* XqK = Xq + (kc * 32) * N;
#pragma unroll
            for (int k = 0; k < 16; k++) {
                int row = arow0 + 2 * k;
                As[row][acol] = mvalid ? WpK[row * Cout] : 0.f;
            }
            // load B tile: 32 rows (cin) x 64 cols (pixel), shifted + masked
#pragma unroll
            for (int k = 0; k < 8; k++) {
                int row = brow0 + 4 * k;
                Bs[row][bcol] = ok ? XqK[row * N] : 0.f;
            }
            __syncthreads();

#pragma unroll
            for (int r = 0; r < 32; r++) {
                float a[8], bb[4];
#pragma unroll
                for (int i = 0; i < 8; i++) a[i] = As[r][ty * 8 + i];
#pragma unroll
                for (int j = 0; j < 4; j++) bb[j] = Bs[r][tx * 4 + j];
#pragma unroll
                for (int i = 0; i < 8; i++)
#pragma unroll
                    for (int j = 0; j < 4; j++) acc[i][j] += a[i] * bb[j];
            }
            __syncthreads();
        }
    }

#pragma unroll
    for (int i = 0; i < 8; i++) {
        int m = m0 + ty * 8 + i;
        if (m < Cout) {
            float bv = bias[m];
#pragma unroll
            for (int j = 0; j < 4; j++) {
                float v = acc[i][j] + bv;
                if (doRelu) v = fmaxf(v, 0.f);
                Y[m * N + n0 + tx * 4 + j] = v;
            }
        }
    }
}

// Postprocess: per (anchor i, pixel n): sigmoid-max/argmax of 80 logits, bbox decode.
__constant__ float c_scale[3] = {1.0f, 1.2599210498948732f, 1.5874010519681994f};
__constant__ float c_sqrt_ratio[3] = {0.7071067811865476f, 1.0f, 1.4142135623730951f};

__global__ void post_kernel(const float* __restrict__ cls, const float* __restrict__ reg,
                            float* __restrict__ out, int N, int HW, int W, int logW,
                            float stride, int aoff) {
    int t = blockIdx.x * blockDim.x + threadIdx.x;
    if (t >= N * NUM_ANCH) return;
    int i = t / N;
    int n = t % N;
    int b = n / HW;
    int p = n % HW;
    int x = p & (W - 1);
    int y = p >> logW;

    // max/argmax over 80 class logits
    float best = -3.4e38f;
    int bi = 0;
#pragma unroll 4
    for (int c = 0; c < NUM_CLASSES; c++) {
        float v = cls[(i * NUM_CLASSES + c) * N + n];
        if (v > best) { best = v; bi = c; }
    }
    float score = 1.f / (1.f + expf(-best));

    float d0 = reg[(i * 4 + 0) * N + n];
    float d1 = reg[(i * 4 + 1) * N + n];
    float d2 = reg[(i * 4 + 2) * N + n];
    float d3 = reg[(i * 4 + 3) * N + n];

    float base = 4.f * stride;
    float sc = c_scale[i % 3];
    float sr = c_sqrt_ratio[i / 3];
    float wa = base * sc / sr;
    float ha = base * sc * sr;
    float cx = (x + 0.5f) * stride;
    float cy = (y + 0.5f) * stride;

    float pcx = cx + d0 * 0.1f * wa;
    float pcy = cy + d1 * 0.1f * ha;
    float pw = expf(d2 * 0.2f) * wa;
    float ph = expf(d3 * 0.2f) * ha;

    int ai = aoff + p * NUM_ANCH + i;
    int gi = b * ATOT + ai;

    out[gi] = score;                                   // scores
    out[BATCH * ATOT + gi] = (float)bi;                // class_id
    float* bx = out + 2 * BATCH * ATOT;                // boxes
    bx[(size_t)gi * 4 + 0] = pcx - 0.5f * pw;
    bx[(size_t)gi * 4 + 1] = pcy - 0.5f * ph;
    bx[(size_t)gi * 4 + 2] = pcx + 0.5f * pw;
    bx[(size_t)gi * 4 + 3] = pcy + 0.5f * ph;
}

// ============================================================================

extern "C" void kernel_launch(void* const* d_in, const int* in_sizes, int n_in,
                              void* d_out, int out_size) {
    (void)in_sizes; (void)n_in; (void)out_size;

    const float* feat[5];
    for (int i = 0; i < 5; i++) feat[i] = (const float*)d_in[i];
    const float* cls_w[5]; const float* cls_b[5];
    const float* reg_w[5]; const float* reg_b[5];
    for (int i = 0; i < 5; i++) {
        cls_w[i] = (const float*)d_in[5 + 2 * i];
        cls_b[i] = (const float*)d_in[6 + 2 * i];
        reg_w[i] = (const float*)d_in[15 + 2 * i];
        reg_b[i] = (const float*)d_in[16 + 2 * i];
    }
    float* out = (float*)d_out;

    float *px, *pa, *pb, *pcls, *preg, *pwt;
    cudaGetSymbolAddress((void**)&px, g_x);
    cudaGetSymbolAddress((void**)&pa, g_a);
    cudaGetSymbolAddress((void**)&pb, g_b);
    cudaGetSymbolAddress((void**)&pcls, g_cls);
    cudaGetSymbolAddress((void**)&preg, g_reg);
    cudaGetSymbolAddress((void**)&pwt, g_wt);

    // weight-transform offsets (floats)
    const size_t CW = 9 * 256 * 256;            // 589824
    const size_t OFF_CLSF = 4 * CW;             // cls final (720)
    const size_t OFF_REG0 = OFF_CLSF + (size_t)9 * 256 * 720;
    const size_t OFF_REGF = OFF_REG0 + 4 * CW;  // reg final (36)

    // weight transforms
    for (int l = 0; l < 4; l++) {
        wt_kernel<<<512, 256>>>(cls_w[l], pwt + l * CW, 256);
        wt_kernel<<<512, 256>>>(reg_w[l], pwt + OFF_REG0 + l * CW, 256);
    }
    wt_kernel<<<1024, 256>>>(cls_w[4], pwt + OFF_CLSF, 720);
    wt_kernel<<<128, 256>>>(reg_w[4], pwt + OFF_REGF, 36);

    struct Lv { int HW, W, logW; float stride; int aoff; };
    const Lv LV[5] = {
        {4096, 64, 6, 8.f, 0},
        {1024, 32, 5, 16.f, 36864},
        {256, 16, 4, 32.f, 46080},
        {64, 8, 3, 64.f, 48384},
        {16, 4, 2, 128.f, 48960},
    };

    for (int lev = 0; lev < 5; lev++) {
        const int HW = LV[lev].HW, W = LV[lev].W, logW = LV[lev].logW;
        const int N = BATCH * HW;
        const int H = W;

        {
            int total = 256 * N;
            int blocks = (total + 255) / 256;
            if (blocks > 4096) blocks = 4096;
            transpose_feat<<<blocks, 256>>>(feat[lev], px, HW, N);
        }

        dim3 g256(N / 64, 2);
        dim3 g720(N / 64, 6);
        dim3 g36(N / 64, 1);

        // cls tower
        conv3x3_kernel<<<g256, 256>>>(pwt + 0 * CW, cls_b[0], px, pa, 256, N, W, logW, H, 1);
        conv3x3_kernel<<<g256, 256>>>(pwt + 1 * CW, cls_b[1], pa, pb, 256, N, W, logW, H, 1);
        conv3x3_kernel<<<g256, 256>>>(pwt + 2 * CW, cls_b[2], pb, pa, 256, N, W, logW, H, 1);
        conv3x3_kernel<<<g256, 256>>>(pwt + 3 * CW, cls_b[3], pa, pb, 256, N, W, logW, H, 1);
        conv3x3_kernel<<<g720, 256>>>(pwt + OFF_CLSF, cls_b[4], pb, pcls, 720, N, W, logW, H, 0);

        // reg tower
        conv3x3_kernel<<<g256, 256>>>(pwt + OFF_REG0 + 0 * CW, reg_b[0], px, pa, 256, N, W, logW, H, 1);
        conv3x3_kernel<<<g256, 256>>>(pwt + OFF_REG0 + 1 * CW, reg_b[1], pa, pb, 256, N, W, logW, H, 1);
        conv3x3_kernel<<<g256, 256>>>(pwt + OFF_REG0 + 2 * CW, reg_b[2], pb, pa, 256, N, W, logW, H, 1);
        conv3x3_kernel<<<g256, 256>>>(pwt + OFF_REG0 + 3 * CW, reg_b[3], pa, pb, 256, N, W, logW, H, 1);
        conv3x3_kernel<<<g36, 256>>>(pwt + OFF_REGF, reg_b[4], pb, preg, 36, N, W, logW, H, 0);

        // postprocess this level
        {
            int total = N * NUM_ANCH;
            int blocks = (total + 255) / 256;
            post_kernel<<<blocks, 256>>>(pcls, preg, out, N, HW, W, logW,
                                         LV[lev].stride, LV[lev].aoff);
        }
    }
}

// round 6
// speedup vs baseline: 1.0330x; 1.0330x over previous
#include <cuda_runtime.h>
#include <cstdint>

// ============================================================================
// RetinaHead: 5 FPN levels, two conv towers (cls 720ch / reg 36ch), postprocess.
// Round 5: 3xTF32 mma implicit-GEMM conv with CHUNKED accumulation:
//   per-BK(32) tensor accumulator folded into fp32 registers via FADD (RNE),
//   defeating the tensor-core's internal truncating accumulation bias.
// ============================================================================

#define NUM_CLASSES 80
#define NUM_ANCH 9
#define ATOT 49104
#define BATCH 8
#define NMAX (256*32768)

__device__ float g_x[NMAX];                 // transposed input feat [256][N]
__device__ float g_a[NMAX];                 // ping
__device__ float g_b[NMAX];                 // pong
__device__ float g_cls[720 * 32768];        // cls logits [720][N]
__device__ float g_reg[36 * 32768];         // reg deltas [36][N]
__device__ float g_wt[6460416];             // transposed weights [kpos*256+cin][cout]

// Weight transform: src (Cout,256,3,3) -> dst [kpos*256+cin][cout]
__global__ void wt_kernel(const float* __restrict__ src, float* __restrict__ dst, int Cout) {
    int total = 9 * 256 * Cout;
    for (int t = blockIdx.x * blockDim.x + threadIdx.x; t < total; t += gridDim.x * blockDim.x) {
        int cout = t % Cout;
        int rem  = t / Cout;
        int cin  = rem % 256;
        int kpos = rem / 256;
        dst[t] = src[(cout * 256 + cin) * 9 + kpos];
    }
}

// Transpose feat (B,256,H,W) -> [256][B*HW]
__global__ void transpose_feat(const float* __restrict__ src, float* __restrict__ dst,
                               int HW, int N) {
    int total = 256 * N;
    for (int t = blockIdx.x * blockDim.x + threadIdx.x; t < total; t += gridDim.x * blockDim.x) {
        int c   = t / N;
        int rem = t % N;
        int b   = rem / HW;
        int p   = rem % HW;
        dst[t] = src[(b * 256 + c) * HW + p];
    }
}

__device__ __forceinline__ float to_tf32(float v) {
    uint32_t u;
    asm("cvt.rna.tf32.f32 %0, %1;" : "=r"(u) : "f"(v));
    return __uint_as_float(u);
}

__device__ __forceinline__ void mma_tf32(float* d, const uint32_t* a, const uint32_t* b) {
    asm volatile(
        "mma.sync.aligned.m16n8k8.row.col.f32.tf32.tf32.f32 "
        "{%0,%1,%2,%3}, {%4,%5,%6,%7}, {%8,%9}, {%0,%1,%2,%3};"
        : "+f"(d[0]), "+f"(d[1]), "+f"(d[2]), "+f"(d[3])
        : "r"(a[0]), "r"(a[1]), "r"(a[2]), "r"(a[3]), "r"(b[0]), "r"(b[1]));
}

// conv3x3 SAME (Cin=256) as implicit GEMM over K=2304. Block tile 128x128x32.
// 8 warps (2 M x 4 N), warp tile 64x32. 3-term tf32 split + chunked accumulation.
#define BK 32
#define KT_TOTAL 72
#define SP 136
#define SMEM_FLOATS (4 * BK * SP)

__global__ void __launch_bounds__(256)
conv3x3_mma(const float* __restrict__ WT, const float* __restrict__ bias,
            const float* __restrict__ X, float* __restrict__ Y,
            int Cout, int N, int W, int logW, int H, int doRelu) {
    extern __shared__ float sm[];
    float* AsH = sm;                    // [BK][SP]
    float* AsL = sm + BK * SP;
    float* BsH = sm + 2 * BK * SP;
    float* BsL = sm + 3 * BK * SP;

    const int tid = threadIdx.x;
    const int n0 = blockIdx.x * 128;
    const int m0 = blockIdx.y * 128;

    const int lane = tid & 31;
    const int warp = tid >> 5;
    const int wm = warp >> 2;
    const int wn = warp & 3;
    const int g = lane >> 2;
    const int t = lane & 3;
    const int mBase = wm * 64;
    const int nBase = wn * 32;

    const int aCol = tid & 127;
    const int aR0  = tid >> 7;
    const bool mvalid = (m0 + aCol) < Cout;
    const int nG = n0 + aCol;
    const int xc = nG & (W - 1);
    const int yc = (nG >> logW) & (H - 1);

    float accF[4][4][4];   // final fp32 accumulators (RNE FADD)
    float accT[4][4][4];   // per-chunk tensor accumulators
#pragma unroll
    for (int mi = 0; mi < 4; mi++)
#pragma unroll
        for (int ni = 0; ni < 4; ni++)
#pragma unroll
            for (int r = 0; r < 4; r++) { accF[mi][ni][r] = 0.f; accT[mi][ni][r] = 0.f; }

    float aReg[16], bReg[16];

    auto loadT = [&](int kt) {
        const float* Aq = WT + (kt * BK + aR0) * Cout + m0 + aCol;
#pragma unroll
        for (int i = 0; i < 16; i++) aReg[i] = mvalid ? Aq[(2 * i) * Cout] : 0.f;
        int kpos = kt >> 3;
        int dy = kpos / 3 - 1;
        int dx = kpos - (kpos / 3) * 3 - 1;
        bool ok = ((unsigned)(xc + dx) < (unsigned)W) && ((unsigned)(yc + dy) < (unsigned)H);
        const float* Bq = X + ((kt & 7) * BK + aR0) * N + nG + dy * W + dx;
#pragma unroll
        for (int i = 0; i < 16; i++) bReg[i] = ok ? Bq[(2 * i) * N] : 0.f;
    };
    auto storeT = [&]() {
#pragma unroll
        for (int i = 0; i < 16; i++) {
            int idx = (aR0 + 2 * i) * SP + aCol;
            float v = aReg[i];
            float h = to_tf32(v);
            AsH[idx] = h;
            AsL[idx] = to_tf32(v - h);
        }
#pragma unroll
        for (int i = 0; i < 16; i++) {
            int idx = (aR0 + 2 * i) * SP + aCol;
            float v = bReg[i];
            float h = to_tf32(v);
            BsH[idx] = h;
            BsL[idx] = to_tf32(v - h);
        }
    };

    loadT(0);
    storeT();
    __syncthreads();

    for (int kt = 0; kt < KT_TOTAL; kt++) {
        if (kt + 1 < KT_TOTAL) loadT(kt + 1);

#pragma unroll
        for (int k8 = 0; k8 < 4; k8++) {
            const int kr = k8 * 8;
            uint32_t aH[4][4], aL[4][4], bH[4][2], bL[4][2];
#pragma unroll
            for (int mi = 0; mi < 4; mi++) {
                int c0 = mBase + mi * 16 + g;
                aH[mi][0] = __float_as_uint(AsH[(kr + t) * SP + c0]);
                aH[mi][1] = __float_as_uint(AsH[(kr + t) * SP + c0 + 8]);
                aH[mi][2] = __float_as_uint(AsH[(kr + t + 4) * SP + c0]);
                aH[mi][3] = __float_as_uint(AsH[(kr + t + 4) * SP + c0 + 8]);
                aL[mi][0] = __float_as_uint(AsL[(kr + t) * SP + c0]);
                aL[mi][1] = __float_as_uint(AsL[(kr + t) * SP + c0 + 8]);
                aL[mi][2] = __float_as_uint(AsL[(kr + t + 4) * SP + c0]);
                aL[mi][3] = __float_as_uint(AsL[(kr + t + 4) * SP + c0 + 8]);
            }
#pragma unroll
            for (int ni = 0; ni < 4; ni++) {
                int c0 = nBase + ni * 8 + g;
                bH[ni][0] = __float_as_uint(BsH[(kr + t) * SP + c0]);
                bH[ni][1] = __float_as_uint(BsH[(kr + t + 4) * SP + c0]);
                bL[ni][0] = __float_as_uint(BsL[(kr + t) * SP + c0]);
                bL[ni][1] = __float_as_uint(BsL[(kr + t + 4) * SP + c0]);
            }
#pragma unroll
            for (int mi = 0; mi < 4; mi++)
#pragma unroll
                for (int ni = 0; ni < 4; ni++) {
                    mma_tf32(accT[mi][ni], aL[mi], bH[ni]);
                    mma_tf32(accT[mi][ni], aH[mi], bL[ni]);
                    mma_tf32(accT[mi][ni], aH[mi], bH[ni]);
                }
        }

        // fold chunk into fp32 accumulators (RNE), reset tensor accumulators
#pragma unroll
        for (int mi = 0; mi < 4; mi++)
#pragma unroll
            for (int ni = 0; ni < 4; ni++)
#pragma unroll
                for (int r = 0; r < 4; r++) {
                    accF[mi][ni][r] += accT[mi][ni][r];
                    accT[mi][ni][r] = 0.f;
                }

        __syncthreads();
        if (kt + 1 < KT_TOTAL) {
            storeT();
        }
        __syncthreads();
    }

#pragma unroll
    for (int mi = 0; mi < 4; mi++) {
        int m_lo = m0 + mBase + mi * 16 + g;
        int m_hi = m_lo + 8;
        float bv_lo = (m_lo < Cout) ? bias[m_lo] : 0.f;
        float bv_hi = (m_hi < Cout) ? bias[m_hi] : 0.f;
#pragma unroll
        for (int ni = 0; ni < 4; ni++) {
            int n = n0 + nBase + ni * 8 + 2 * t;
            float* a4 = accF[mi][ni];
            if (m_lo < Cout) {
                float v0 = a4[0] + bv_lo, v1 = a4[1] + bv_lo;
                if (doRelu) { v0 = fmaxf(v0, 0.f); v1 = fmaxf(v1, 0.f); }
                Y[m_lo * N + n] = v0;
                Y[m_lo * N + n + 1] = v1;
            }
            if (m_hi < Cout) {
                float v2 = a4[2] + bv_hi, v3 = a4[3] + bv_hi;
                if (doRelu) { v2 = fmaxf(v2, 0.f); v3 = fmaxf(v3, 0.f); }
                Y[m_hi * N + n] = v2;
                Y[m_hi * N + n + 1] = v3;
            }
        }
    }
}

// Postprocess
__constant__ float c_scale[3] = {1.0f, 1.2599210498948732f, 1.5874010519681994f};
__constant__ float c_sqrt_ratio[3] = {0.7071067811865476f, 1.0f, 1.4142135623730951f};

__global__ void post_kernel(const float* __restrict__ cls, const float* __restrict__ reg,
                            float* __restrict__ out, int N, int HW, int W, int logW,
                            float stride, int aoff) {
    int t = blockIdx.x * blockDim.x + threadIdx.x;
    if (t >= N * NUM_ANCH) return;
    int i = t / N;
    int n = t % N;
    int b = n / HW;
    int p = n % HW;
    int x = p & (W - 1);
    int y = p >> logW;

    float best = -3.4e38f;
    int bi = 0;
#pragma unroll 4
    for (int c = 0; c < NUM_CLASSES; c++) {
        float v = cls[(i * NUM_CLASSES + c) * N + n];
        if (v > best) { best = v; bi = c; }
    }
    float score = 1.f / (1.f + expf(-best));

    float d0 = reg[(i * 4 + 0) * N + n];
    float d1 = reg[(i * 4 + 1) * N + n];
    float d2 = reg[(i * 4 + 2) * N + n];
    float d3 = reg[(i * 4 + 3) * N + n];

    float base = 4.f * stride;
    float sc = c_scale[i % 3];
    float sr = c_sqrt_ratio[i / 3];
    float wa = base * sc / sr;
    float ha = base * sc * sr;
    float cx = (x + 0.5f) * stride;
    float cy = (y + 0.5f) * stride;

    float pcx = cx + d0 * 0.1f * wa;
    float pcy = cy + d1 * 0.1f * ha;
    float pw = expf(d2 * 0.2f) * wa;
    float ph = expf(d3 * 0.2f) * ha;

    int ai = aoff + p * NUM_ANCH + i;
    int gi = b * ATOT + ai;

    out[gi] = score;
    out[BATCH * ATOT + gi] = (float)bi;
    float* bx = out + 2 * BATCH * ATOT;
    bx[(size_t)gi * 4 + 0] = pcx - 0.5f * pw;
    bx[(size_t)gi * 4 + 1] = pcy - 0.5f * ph;
    bx[(size_t)gi * 4 + 2] = pcx + 0.5f * pw;
    bx[(size_t)gi * 4 + 3] = pcy + 0.5f * ph;
}

// ============================================================================

extern "C" void kernel_launch(void* const* d_in, const int* in_sizes, int n_in,
                              void* d_out, int out_size) {
    (void)in_sizes; (void)n_in; (void)out_size;

    const float* feat[5];
    for (int i = 0; i < 5; i++) feat[i] = (const float*)d_in[i];
    const float* cls_w[5]; const float* cls_b[5];
    const float* reg_w[5]; const float* reg_b[5];
    for (int i = 0; i < 5; i++) {
        cls_w[i] = (const float*)d_in[5 + 2 * i];
        cls_b[i] = (const float*)d_in[6 + 2 * i];
        reg_w[i] = (const float*)d_in[15 + 2 * i];
        reg_b[i] = (const float*)d_in[16 + 2 * i];
    }
    float* out = (float*)d_out;

    float *px, *pa, *pb, *pcls, *preg, *pwt;
    cudaGetSymbolAddress((void**)&px, g_x);
    cudaGetSymbolAddress((void**)&pa, g_a);
    cudaGetSymbolAddress((void**)&pb, g_b);
    cudaGetSymbolAddress((void**)&pcls, g_cls);
    cudaGetSymbolAddress((void**)&preg, g_reg);
    cudaGetSymbolAddress((void**)&pwt, g_wt);

    const size_t SMEM_BYTES = SMEM_FLOATS * sizeof(float);   // 69,632
    static int attr_done = 0;
    if (!attr_done) {
        cudaFuncSetAttribute(conv3x3_mma, cudaFuncAttributeMaxDynamicSharedMemorySize,
                             (int)SMEM_BYTES);
        attr_done = 1;
    }

    const size_t CW = 9 * 256 * 256;
    const size_t OFF_CLSF = 4 * CW;
    const size_t OFF_REG0 = OFF_CLSF + (size_t)9 * 256 * 720;
    const size_t OFF_REGF = OFF_REG0 + 4 * CW;

    for (int l = 0; l < 4; l++) {
        wt_kernel<<<512, 256>>>(cls_w[l], pwt + l * CW, 256);
        wt_kernel<<<512, 256>>>(reg_w[l], pwt + OFF_REG0 + l * CW, 256);
    }
    wt_kernel<<<1024, 256>>>(cls_w[4], pwt + OFF_CLSF, 720);
    wt_kernel<<<128, 256>>>(reg_w[4], pwt + OFF_REGF, 36);

    struct Lv { int HW, W, logW; float stride; int aoff; };
    const Lv LV[5] = {
        {4096, 64, 6, 8.f, 0},
        {1024, 32, 5, 16.f, 36864},
        {256, 16, 4, 32.f, 46080},
        {64, 8, 3, 64.f, 48384},
        {16, 4, 2, 128.f, 48960},
    };

    for (int lev = 0; lev < 5; lev++) {
        const int HW = LV[lev].HW, W = LV[lev].W, logW = LV[lev].logW;
        const int N = BATCH * HW;
        const int H = W;

        {
            int total = 256 * N;
            int blocks = (total + 255) / 256;
            if (blocks > 4096) blocks = 4096;
            transpose_feat<<<blocks, 256>>>(feat[lev], px, HW, N);
        }

        dim3 g256(N / 128, 2);
        dim3 g720(N / 128, 6);
        dim3 g36(N / 128, 1);

        // cls tower
        conv3x3_mma<<<g256, 256, SMEM_BYTES>>>(pwt + 0 * CW, cls_b[0], px, pa, 256, N, W, logW, H, 1);
        conv3x3_mma<<<g256, 256, SMEM_BYTES>>>(pwt + 1 * CW, cls_b[1], pa, pb, 256, N, W, logW, H, 1);
        conv3x3_mma<<<g256, 256, SMEM_BYTES>>>(pwt + 2 * CW, cls_b[2], pb, pa, 256, N, W, logW, H, 1);
        conv3x3_mma<<<g256, 256, SMEM_BYTES>>>(pwt + 3 * CW, cls_b[3], pa, pb, 256, N, W, logW, H, 1);
        conv3x3_mma<<<g720, 256, SMEM_BYTES>>>(pwt + OFF_CLSF, cls_b[4], pb, pcls, 720, N, W, logW, H, 0);

        // reg tower
        conv3x3_mma<<<g256, 256, SMEM_BYTES>>>(pwt + OFF_REG0 + 0 * CW, reg_b[0], px, pa, 256, N, W, logW, H, 1);
        conv3x3_mma<<<g256, 256, SMEM_BYTES>>>(pwt + OFF_REG0 + 1 * CW, reg_b[1], pa, pb, 256, N, W, logW, H, 1);
        conv3x3_mma<<<g256, 256, SMEM_BYTES>>>(pwt + OFF_REG0 + 2 * CW, reg_b[2], pb, pa, 256, N, W, logW, H, 1);
        conv3x3_mma<<<g256, 256, SMEM_BYTES>>>(pwt + OFF_REG0 + 3 * CW, reg_b[3], pa, pb, 256, N, W, logW, H, 1);
        conv3x3_mma<<<g36, 256, SMEM_BYTES>>>(pwt + OFF_REGF, reg_b[4], pb, preg, 36, N, W, logW, H, 0);

        {
            int total = N * NUM_ANCH;
            int blocks = (total + 255) / 256;
            post_kernel<<<blocks, 256>>>(pcls, preg, out, N, HW, W, logW,
                                         LV[lev].stride, LV[lev].aoff);
        }
    }
}